// round 4
// baseline (speedup 1.0000x reference)
#include <cuda_runtime.h>
#include <cstdint>

#define Bb     2
#define LL     2048
#define DM     512
#define ED_    1024
#define NS     16
#define DTR    32
#define DFF    1024
#define BLr    (Bb*LL)            /* 4096 rows */

typedef unsigned long long ull;

/* ------------------------------------------------------------------ */
/* scratch (per-direction where needed)                                */
/* ------------------------------------------------------------------ */
__device__ float g_xb   [BLr*DM];
__device__ float g_xz   [2*BLr*2*ED_];
__device__ float g_xc   [2*BLr*ED_];
__device__ float g_dbl  [2*BLr*64];
__device__ float g_delta[2*BLr*ED_];
__device__ float g_y    [2*BLr*ED_];
__device__ float g_U    [2*BLr*DM];
__device__ float g_Vh   [2*BLr*DFF];
__device__ float g_V2   [2*BLr*DM];

/* ------------------------------------------------------------------ */
__device__ __forceinline__ float softplusf(float x) {
    return fmaxf(x, 0.f) + log1pf(expf(-fabsf(x)));
}
__device__ __forceinline__ float siluf(float x) {
    return x / (1.f + __expf(-x));
}

/* packed fp32x2 helpers (Blackwell FFMA2) */
__device__ __forceinline__ ull fma2(ull a, ull b, ull c) {
    ull d;
    asm("fma.rn.f32x2 %0, %1, %2, %3;" : "=l"(d) : "l"(a), "l"(b), "l"(c));
    return d;
}
__device__ __forceinline__ ull packf2(float lo, float hi) {
    ull r;
    asm("mov.b64 %0, {%1, %2};" : "=l"(r) : "f"(lo), "f"(hi));
    return r;
}
__device__ __forceinline__ float2 unpackf2(ull v) {
    float lo, hi;
    asm("mov.b64 {%0, %1}, %2;" : "=f"(lo), "=f"(hi) : "l"(v));
    return make_float2(lo, hi);
}

/* ================= f32x2 GEMM ====================================== */
/* C[M,N] = A[M,K](lda) @ B[K,N] fp32, full precision.                 */
/* 128x128x16 tiles, 256 threads, 8x8 per thread via FFMA2.            */
/* ep: 0 none, 1 bias+relu, 2 bias, 3 softplus(bias+x)                 */
/* requires M%128==0, N%128==0, K%16==0                                 */

__global__ void __launch_bounds__(256, 2)
f2_gemm(const float* __restrict__ A, int lda,
        const float* __restrict__ B, int N, int K,
        float* __restrict__ C, const float* __restrict__ bias, int ep)
{
    __shared__ float As[2][16][132];   /* k-major: As[k][m] */
    __shared__ float Bs[2][16][132];   /* Bs[k][n]          */

    const int tid = threadIdx.x;
    const int m0 = blockIdx.y * 128;
    const int n0 = blockIdx.x * 128;
    const int tm = tid >> 4;          /* 0..15 */
    const int tn = tid & 15;          /* 0..15 */

    const int arow = tid >> 1;            /* 0..127 */
    const int acol = (tid & 1) * 8;       /* 0 or 8 */
    const int brow = tid >> 4;            /* 0..15  */
    const int bcol = (tid & 15) * 8;      /* 0..120 */

    const float* gA = A + (size_t)(m0 + arow) * lda + acol;
    const float* gB = B + (size_t)brow * N + n0 + bcol;

    float4 a0, a1, b0, b1;

    /* prolog: tile 0 */
    a0 = *(const float4*)gA;  a1 = *(const float4*)(gA + 4);
    b0 = *(const float4*)gB;  b1 = *(const float4*)(gB + 4);
    As[0][acol + 0][arow] = a0.x;  As[0][acol + 1][arow] = a0.y;
    As[0][acol + 2][arow] = a0.z;  As[0][acol + 3][arow] = a0.w;
    As[0][acol + 4][arow] = a1.x;  As[0][acol + 5][arow] = a1.y;
    As[0][acol + 6][arow] = a1.z;  As[0][acol + 7][arow] = a1.w;
    *(float4*)&Bs[0][brow][bcol]     = b0;
    *(float4*)&Bs[0][brow][bcol + 4] = b1;
    __syncthreads();

    ull acc[4][8];
#pragma unroll
    for (int i = 0; i < 4; ++i)
#pragma unroll
        for (int j = 0; j < 8; ++j) acc[i][j] = 0ull;

    const int NIT = K >> 4;
    for (int it = 0; it < NIT; ++it) {
        if (it + 1 < NIT) {
            const float* pA = gA + (it + 1) * 16;
            a0 = *(const float4*)pA;  a1 = *(const float4*)(pA + 4);
            const float* pB = gB + (size_t)(it + 1) * 16 * N;
            b0 = *(const float4*)pB;  b1 = *(const float4*)(pB + 4);
        }
        const int buf = it & 1;
#pragma unroll
        for (int k = 0; k < 16; ++k) {
            /* A: 4 natural m-pairs (64-bit loads) */
            const longlong2* ap = (const longlong2*)&As[buf][k][tm * 8];
            longlong2 al0 = ap[0], al1 = ap[1];
            ull a2[4] = {(ull)al0.x, (ull)al0.y, (ull)al1.x, (ull)al1.y};
            /* B: 8 values duplicated */
            float4 q0 = *(const float4*)&Bs[buf][k][tn * 8];
            float4 q1 = *(const float4*)&Bs[buf][k][tn * 8 + 4];
            ull b2[8];
            b2[0] = packf2(q0.x, q0.x);  b2[1] = packf2(q0.y, q0.y);
            b2[2] = packf2(q0.z, q0.z);  b2[3] = packf2(q0.w, q0.w);
            b2[4] = packf2(q1.x, q1.x);  b2[5] = packf2(q1.y, q1.y);
            b2[6] = packf2(q1.z, q1.z);  b2[7] = packf2(q1.w, q1.w);
#pragma unroll
            for (int i = 0; i < 4; ++i)
#pragma unroll
                for (int j = 0; j < 8; ++j)
                    acc[i][j] = fma2(a2[i], b2[j], acc[i][j]);
        }
        if (it + 1 < NIT) {
            const int nb = buf ^ 1;
            As[nb][acol + 0][arow] = a0.x;  As[nb][acol + 1][arow] = a0.y;
            As[nb][acol + 2][arow] = a0.z;  As[nb][acol + 3][arow] = a0.w;
            As[nb][acol + 4][arow] = a1.x;  As[nb][acol + 5][arow] = a1.y;
            As[nb][acol + 6][arow] = a1.z;  As[nb][acol + 7][arow] = a1.w;
            *(float4*)&Bs[nb][brow][bcol]     = b0;
            *(float4*)&Bs[nb][brow][bcol + 4] = b1;
        }
        __syncthreads();
    }

    /* ---- epilogue: 8x8 block at (m0+tm*8, n0+tn*8) ---- */
    const int crow = m0 + tm * 8;
    const int ccol = n0 + tn * 8;
    float bv[8];
    if (ep) {
        float4 q0 = *(const float4*)(bias + ccol);
        float4 q1 = *(const float4*)(bias + ccol + 4);
        bv[0] = q0.x; bv[1] = q0.y; bv[2] = q0.z; bv[3] = q0.w;
        bv[4] = q1.x; bv[5] = q1.y; bv[6] = q1.z; bv[7] = q1.w;
    } else {
#pragma unroll
        for (int j = 0; j < 8; ++j) bv[j] = 0.f;
    }

#pragma unroll
    for (int i = 0; i < 4; ++i) {
        float r0[8], r1[8];
#pragma unroll
        for (int j = 0; j < 8; ++j) {
            float2 v = unpackf2(acc[i][j]);
            r0[j] = v.x + bv[j];
            r1[j] = v.y + bv[j];
        }
        if (ep == 1) {
#pragma unroll
            for (int j = 0; j < 8; ++j) {
                r0[j] = fmaxf(r0[j], 0.f);
                r1[j] = fmaxf(r1[j], 0.f);
            }
        } else if (ep == 3) {
#pragma unroll
            for (int j = 0; j < 8; ++j) {
                r0[j] = softplusf(r0[j]);
                r1[j] = softplusf(r1[j]);
            }
        }
        float* p0 = C + (size_t)(crow + 2 * i)     * N + ccol;
        float* p1 = C + (size_t)(crow + 2 * i + 1) * N + ccol;
        *(float4*)p0       = make_float4(r0[0], r0[1], r0[2], r0[3]);
        *(float4*)(p0 + 4) = make_float4(r0[4], r0[5], r0[6], r0[7]);
        *(float4*)p1       = make_float4(r1[0], r1[1], r1[2], r1[3]);
        *(float4*)(p1 + 4) = make_float4(r1[4], r1[5], r1[6], r1[7]);
    }
}

/* ================= SIMT GEMM (dbl: N=64) =========================== */
__global__ __launch_bounds__(256)
void gemm_kernel(const float* __restrict__ A, int lda,
                 const float* __restrict__ B, int N, int K,
                 float* __restrict__ C)
{
    __shared__ float As[16][68];
    __shared__ float Bs[16][68];

    const int tid  = threadIdx.x;
    const int tx   = tid & 15;
    const int ty   = tid >> 4;
    const int row0 = blockIdx.y * 64;
    const int col0 = blockIdx.x * 64;

    const int ar = tid >> 2;
    const int ak = (tid & 3) << 2;
    const int bk = tid >> 4;
    const int bn = (tid & 15) << 2;

    float acc[4][4];
#pragma unroll
    for (int i = 0; i < 4; ++i)
#pragma unroll
        for (int j = 0; j < 4; ++j) acc[i][j] = 0.f;

    for (int k0 = 0; k0 < K; k0 += 16) {
        float4 av = *(const float4*)(A + (size_t)(row0 + ar) * lda + k0 + ak);
        As[ak + 0][ar] = av.x;
        As[ak + 1][ar] = av.y;
        As[ak + 2][ar] = av.z;
        As[ak + 3][ar] = av.w;
        *(float4*)&Bs[bk][bn] =
            *(const float4*)(B + (size_t)(k0 + bk) * N + col0 + bn);
        __syncthreads();

#pragma unroll
        for (int kk = 0; kk < 16; ++kk) {
            float4 a = *(const float4*)&As[kk][ty << 2];
            float4 b = *(const float4*)&Bs[kk][tx << 2];
            float ai[4] = {a.x, a.y, a.z, a.w};
            float bj[4] = {b.x, b.y, b.z, b.w};
#pragma unroll
            for (int i = 0; i < 4; ++i)
#pragma unroll
                for (int j = 0; j < 4; ++j)
                    acc[i][j] = fmaf(ai[i], bj[j], acc[i][j]);
        }
        __syncthreads();
    }

    const int m0 = row0 + (ty << 2);
    const int n0 = col0 + (tx << 2);
#pragma unroll
    for (int i = 0; i < 4; ++i)
        *(float4*)(C + (size_t)(m0 + i) * N + n0) =
            make_float4(acc[i][0], acc[i][1], acc[i][2], acc[i][3]);
}

/* ------------------------------------------------------------------ */
__global__ void flip_kernel(const float* __restrict__ x, float* __restrict__ xb)
{
    int idx = blockIdx.x * 256 + threadIdx.x;
    int c = idx & 127;
    int r = idx >> 7;
    int b = r >> 11;
    int l = r & 2047;
    ((float4*)xb)[idx] =
        ((const float4*)x)[(size_t)(((b << 11) + (2047 - l)) << 7) + c];
}

/* ------------------------------------------------------------------ */
__global__ void conv_silu_kernel(const float* __restrict__ xz,
                                 const float* __restrict__ cw,
                                 const float* __restrict__ cb,
                                 float* __restrict__ xc)
{
    int idx = blockIdx.x * blockDim.x + threadIdx.x;
    int e = idx & 1023;
    int r = idx >> 10;
    int l = r & 2047;
    int b = r >> 11;
    float s = cb[e];
#pragma unroll
    for (int k = 0; k < 4; ++k) {
        int ll = l + k - 3;
        if (ll >= 0)
            s = fmaf(xz[((size_t)((b << 11) + ll) << 11) + e], cw[(e << 2) + k], s);
    }
    xc[idx] = siluf(s);
}

/* ------------------------------------------------------------------ */
__global__ __launch_bounds__(256)
void scan_kernel(const float* __restrict__ delta, const float* __restrict__ xc,
                 const float* __restrict__ dbl,   const float* __restrict__ xz,
                 const float* __restrict__ A_log, const float* __restrict__ Dp,
                 float* __restrict__ y)
{
    int warp  = (blockIdx.x * blockDim.x + threadIdx.x) >> 5;
    int lane  = threadIdx.x & 31;
    int half  = lane >> 4;
    int n     = lane & 15;
    int chain = (warp << 1) + half;
    int b = chain >> 10;
    int e = chain & 1023;

    const float a  = -expf(A_log[(e << 4) + n]);
    const float dc = Dp[e];
    float h = 0.f;
    const int rowbase = b << 11;

    for (int l0 = 0; l0 < LL; l0 += 4) {
        float d[4], xv[4], bv[4], cv[4];
#pragma unroll
        for (int s = 0; s < 4; ++s) {
            int row = rowbase + l0 + s;
            d[s]  = __ldg(&delta[(size_t)(row << 10) + e]);
            xv[s] = __ldg(&xc   [(size_t)(row << 10) + e]);
            bv[s] = __ldg(&dbl  [(row << 6) + 32 + n]);
            cv[s] = __ldg(&dbl  [(row << 6) + 48 + n]);
        }
        float p[4];
#pragma unroll
        for (int s = 0; s < 4; ++s) {
            float dA = __expf(d[s] * a);
            h = fmaf(dA, h, d[s] * xv[s] * bv[s]);
            p[s] = h * cv[s];
        }
#pragma unroll
        for (int o = 1; o < 16; o <<= 1) {
#pragma unroll
            for (int s = 0; s < 4; ++s)
                p[s] += __shfl_xor_sync(0xffffffffu, p[s], o);
        }
        if (n == 0) {
#pragma unroll
            for (int s = 0; s < 4; ++s) {
                int row = rowbase + l0 + s;
                float zv = xz[((size_t)row << 11) + 1024 + e];
                y[(size_t)(row << 10) + e] = (p[s] + xv[s] * dc) * siluf(zv);
            }
        }
    }
}

/* ------------------------------------------------------------------ */
__global__ __launch_bounds__(128)
void ln_kernel(float* __restrict__ U, const float* __restrict__ g,
               const float* __restrict__ bb)
{
    int row = blockIdx.x;
    float4* p = (float4*)(U + (size_t)row * DM);
    int tid = threadIdx.x;
    int lane = tid & 31, w = tid >> 5;
    __shared__ float red[4];

    float4 v = p[tid];
    float s = v.x + v.y + v.z + v.w;
#pragma unroll
    for (int o = 16; o; o >>= 1) s += __shfl_xor_sync(0xffffffffu, s, o);
    if (!lane) red[w] = s;
    __syncthreads();
    float mu = (red[0] + red[1] + red[2] + red[3]) * (1.f / 512.f);

    float dx = v.x - mu, dy = v.y - mu, dz = v.z - mu, dw = v.w - mu;
    float s2 = dx*dx + dy*dy + dz*dz + dw*dw;
#pragma unroll
    for (int o = 16; o; o >>= 1) s2 += __shfl_xor_sync(0xffffffffu, s2, o);
    __syncthreads();
    if (!lane) red[w] = s2;
    __syncthreads();
    float var  = (red[0] + red[1] + red[2] + red[3]) * (1.f / 512.f);
    float rstd = rsqrtf(var + 1e-5f);

    int c = tid << 2;
    float4 go = *(const float4*)(g + c);
    float4 bo = *(const float4*)(bb + c);
    float4 o;
    o.x = dx * rstd * go.x + bo.x;
    o.y = dy * rstd * go.y + bo.y;
    o.z = dz * rstd * go.z + bo.z;
    o.w = dw * rstd * go.w + bo.w;
    p[tid] = o;
}

/* ------------------------------------------------------------------ */
__global__ void final_kernel(const float* __restrict__ V2,
                             const float* __restrict__ U,
                             float* __restrict__ out)
{
    int idx = blockIdx.x * 256 + threadIdx.x;
    const int off = (BLr * DM) >> 2;
    float4 a = ((const float4*)V2)[idx];
    float4 b = ((const float4*)V2)[idx + off];
    float4 c = ((const float4*)U)[idx];
    float4 d = ((const float4*)U)[idx + off];
    float4 o;
    o.x = a.x + b.x + c.x + d.x;
    o.y = a.y + b.y + c.y + d.y;
    o.z = a.z + b.z + c.z + d.z;
    o.w = a.w + b.w + c.w + d.w;
    ((float4*)out)[idx] = o;
}

/* ------------------------------------------------------------------ */
extern "C" void kernel_launch(void* const* d_in, const int* in_sizes, int n_in,
                              void* d_out, int out_size)
{
    (void)in_sizes; (void)n_in; (void)out_size;

    float *xb, *xz, *xc, *dbl, *delta, *y, *U, *Vh, *V2;
    cudaGetSymbolAddress((void**)&xb,    g_xb);
    cudaGetSymbolAddress((void**)&xz,    g_xz);
    cudaGetSymbolAddress((void**)&xc,    g_xc);
    cudaGetSymbolAddress((void**)&dbl,   g_dbl);
    cudaGetSymbolAddress((void**)&delta, g_delta);
    cudaGetSymbolAddress((void**)&y,     g_y);
    cudaGetSymbolAddress((void**)&U,     g_U);
    cudaGetSymbolAddress((void**)&Vh,    g_Vh);
    cudaGetSymbolAddress((void**)&V2,    g_V2);

    const float* x = (const float*)d_in[0];
    const float* norm1_g = (const float*)d_in[19];
    const float* norm1_b = (const float*)d_in[20];
    const float* ffn_w1  = (const float*)d_in[23];
    const float* ffn_b1  = (const float*)d_in[24];
    const float* ffn_w2  = (const float*)d_in[25];
    const float* ffn_b2  = (const float*)d_in[26];

    const float* W[2][9];
    for (int dir = 0; dir < 2; ++dir)
        for (int k = 0; k < 9; ++k)
            W[dir][k] = (const float*)d_in[1 + dir * 9 + k];

    /* per-direction buffer views */
    float* XZ[2]  = {xz,    xz    + (size_t)BLr * 2 * ED_};
    float* XC[2]  = {xc,    xc    + (size_t)BLr * ED_};
    float* DB[2]  = {dbl,   dbl   + (size_t)BLr * 64};
    float* DE[2]  = {delta, delta + (size_t)BLr * ED_};
    float* Y[2]   = {y,     y     + (size_t)BLr * ED_};

    /* launch #1: flip */
    flip_kernel<<<(BLr * DM / 4) / 256, 256>>>(x, xb);

    /* #2: xz1 = xb @ in_w_b (dir 1) */
    f2_gemm<<<dim3(2 * ED_ / 128, BLr / 128), 256>>>(
        xb, DM, W[1][0], 2 * ED_, DM, XZ[1], nullptr, 0);

    /* #3: conv1 */
    conv_silu_kernel<<<(BLr * ED_) / 256, 256>>>(XZ[1], W[1][1], W[1][2], XC[1]);

    /* #4: xz0 = x @ in_w_f  (dir 0) — profiled launch */
    f2_gemm<<<dim3(2 * ED_ / 128, BLr / 128), 256>>>(
        x, DM, W[0][0], 2 * ED_, DM, XZ[0], nullptr, 0);

    /* #5: conv0 */
    conv_silu_kernel<<<(BLr * ED_) / 256, 256>>>(XZ[0], W[0][1], W[0][2], XC[0]);

    for (int dir = 0; dir < 2; ++dir) {
        /* dbl = xc @ xproj_w : 4096 x 64 x 1024 (SIMT, N=64) */
        gemm_kernel<<<dim3(1, BLr / 64), 256>>>(
            XC[dir], ED_, W[dir][3], 64, ED_, DB[dir]);

        /* delta = softplus(dt @ dt_w + dt_b) : 4096 x 1024 x 32 */
        f2_gemm<<<dim3(ED_ / 128, BLr / 128), 256>>>(
            DB[dir], 64, W[dir][4], ED_, DTR, DE[dir], W[dir][5], 3);

        /* selective scan (fused silu(z) gate) */
        scan_kernel<<<128, 256>>>(DE[dir], XC[dir], DB[dir], XZ[dir],
                                  W[dir][6], W[dir][7], Y[dir]);

        /* m = y @ out_w : 4096 x 512 x 1024 */
        f2_gemm<<<dim3(DM / 128, BLr / 128), 256>>>(
            Y[dir], ED_, W[dir][8], DM, ED_, U + (size_t)dir * BLr * DM,
            nullptr, 0);

        if (dir == 0)
            ln_kernel<<<BLr, 128>>>(U, norm1_g, norm1_b);
    }

    /* FFN batched over both directions: 8192 rows */
    f2_gemm<<<dim3(DFF / 128, 2 * BLr / 128), 256>>>(
        U, DM, ffn_w1, DFF, DM, Vh, ffn_b1, 1);
    f2_gemm<<<dim3(DM / 128, 2 * BLr / 128), 256>>>(
        Vh, DFF, ffn_w2, DM, DFF, V2, ffn_b2, 2);

    final_kernel<<<(BLr * DM / 4) / 256, 256>>>(V2, U, (float*)d_out);
}

// round 5
// speedup vs baseline: 2.1696x; 2.1696x over previous
#include <cuda_runtime.h>
#include <cstdint>

#define Bb     2
#define LL     2048
#define DM     512
#define ED_    1024
#define NS     16
#define DTR    32
#define DFF    1024
#define BLr    (Bb*LL)            /* 4096 rows */
#define NCHUNK 16
#define CLEN   (LL/NCHUNK)        /* 128 */
#define NCHAIN 2048               /* Bb*ED_ chains per direction */

typedef unsigned long long ull;

/* ------------------------------------------------------------------ */
/* scratch                                                             */
/* ------------------------------------------------------------------ */
__device__ float g_xb   [BLr*DM];
__device__ float g_xz   [2*BLr*2*ED_];
__device__ float g_xc   [2*BLr*ED_];
__device__ float g_dbl  [2*BLr*64];
__device__ float g_delta[2*BLr*ED_];
__device__ float g_y    [2*BLr*ED_];
__device__ float g_U    [2*BLr*DM];
__device__ float g_Vh   [2*BLr*DFF];
__device__ float g_V2   [2*BLr*DM];
__device__ float g_hloc [2*NCHUNK*NCHAIN*NS];
__device__ float g_aprod[2*NCHUNK*NCHAIN*NS];
__device__ float g_hin  [2*NCHUNK*NCHAIN*NS];

/* ------------------------------------------------------------------ */
__device__ __forceinline__ float softplusf(float x) {
    return fmaxf(x, 0.f) + log1pf(expf(-fabsf(x)));
}
__device__ __forceinline__ float siluf(float x) {
    return x / (1.f + __expf(-x));
}

/* packed fp32x2 helpers (Blackwell FFMA2) */
__device__ __forceinline__ ull fma2(ull a, ull b, ull c) {
    ull d;
    asm("fma.rn.f32x2 %0, %1, %2, %3;" : "=l"(d) : "l"(a), "l"(b), "l"(c));
    return d;
}
__device__ __forceinline__ ull packf2(float lo, float hi) {
    ull r;
    asm("mov.b64 %0, {%1, %2};" : "=l"(r) : "f"(lo), "f"(hi));
    return r;
}
__device__ __forceinline__ float2 unpackf2(ull v) {
    float lo, hi;
    asm("mov.b64 {%0, %1}, %2;" : "=f"(lo), "=f"(hi) : "l"(v));
    return make_float2(lo, hi);
}

/* ================= f32x2 GEMM (z-batched over 2 dirs) ============== */
/* C[z][M,N] = A_z[M,K](lda) @ B_z[K,N] fp32.                          */
/* 128x128x16 tiles, 256 threads, 8x8 per thread via FFMA2.            */
/* ep: 0 none, 1 bias+relu, 2 bias, 3 softplus(bias+x)                 */

__global__ void __launch_bounds__(256, 2)
f2_gemm(const float* __restrict__ A0, const float* __restrict__ A1, int lda,
        const float* __restrict__ B0, const float* __restrict__ B1,
        int N, int K,
        float* __restrict__ C, size_t strideC,
        const float* __restrict__ bias0, const float* __restrict__ bias1,
        int ep)
{
    __shared__ float As[2][16][132];
    __shared__ float Bs[2][16][132];

    const int z = blockIdx.z;
    const float* A = z ? A1 : A0;
    const float* B = z ? B1 : B0;
    const float* bias = z ? bias1 : bias0;
    C += (size_t)z * strideC;

    const int tid = threadIdx.x;
    const int m0 = blockIdx.y * 128;
    const int n0 = blockIdx.x * 128;
    const int tm = tid >> 4;
    const int tn = tid & 15;

    const int arow = tid >> 1;
    const int acol = (tid & 1) * 8;
    const int brow = tid >> 4;
    const int bcol = (tid & 15) * 8;

    const float* gA = A + (size_t)(m0 + arow) * lda + acol;
    const float* gB = B + (size_t)brow * N + n0 + bcol;

    float4 a0, a1, b0, b1;

    a0 = *(const float4*)gA;  a1 = *(const float4*)(gA + 4);
    b0 = *(const float4*)gB;  b1 = *(const float4*)(gB + 4);
    As[0][acol + 0][arow] = a0.x;  As[0][acol + 1][arow] = a0.y;
    As[0][acol + 2][arow] = a0.z;  As[0][acol + 3][arow] = a0.w;
    As[0][acol + 4][arow] = a1.x;  As[0][acol + 5][arow] = a1.y;
    As[0][acol + 6][arow] = a1.z;  As[0][acol + 7][arow] = a1.w;
    *(float4*)&Bs[0][brow][bcol]     = b0;
    *(float4*)&Bs[0][brow][bcol + 4] = b1;
    __syncthreads();

    ull acc[4][8];
#pragma unroll
    for (int i = 0; i < 4; ++i)
#pragma unroll
        for (int j = 0; j < 8; ++j) acc[i][j] = 0ull;

    const int NIT = K >> 4;
    for (int it = 0; it < NIT; ++it) {
        if (it + 1 < NIT) {
            const float* pA = gA + (it + 1) * 16;
            a0 = *(const float4*)pA;  a1 = *(const float4*)(pA + 4);
            const float* pB = gB + (size_t)(it + 1) * 16 * N;
            b0 = *(const float4*)pB;  b1 = *(const float4*)(pB + 4);
        }
        const int buf = it & 1;
#pragma unroll
        for (int k = 0; k < 16; ++k) {
            const longlong2* ap = (const longlong2*)&As[buf][k][tm * 8];
            longlong2 al0 = ap[0], al1 = ap[1];
            ull a2[4] = {(ull)al0.x, (ull)al0.y, (ull)al1.x, (ull)al1.y};
            float4 q0 = *(const float4*)&Bs[buf][k][tn * 8];
            float4 q1 = *(const float4*)&Bs[buf][k][tn * 8 + 4];
            ull b2[8];
            b2[0] = packf2(q0.x, q0.x);  b2[1] = packf2(q0.y, q0.y);
            b2[2] = packf2(q0.z, q0.z);  b2[3] = packf2(q0.w, q0.w);
            b2[4] = packf2(q1.x, q1.x);  b2[5] = packf2(q1.y, q1.y);
            b2[6] = packf2(q1.z, q1.z);  b2[7] = packf2(q1.w, q1.w);
#pragma unroll
            for (int i = 0; i < 4; ++i)
#pragma unroll
                for (int j = 0; j < 8; ++j)
                    acc[i][j] = fma2(a2[i], b2[j], acc[i][j]);
        }
        if (it + 1 < NIT) {
            const int nb = buf ^ 1;
            As[nb][acol + 0][arow] = a0.x;  As[nb][acol + 1][arow] = a0.y;
            As[nb][acol + 2][arow] = a0.z;  As[nb][acol + 3][arow] = a0.w;
            As[nb][acol + 4][arow] = a1.x;  As[nb][acol + 5][arow] = a1.y;
            As[nb][acol + 6][arow] = a1.z;  As[nb][acol + 7][arow] = a1.w;
            *(float4*)&Bs[nb][brow][bcol]     = b0;
            *(float4*)&Bs[nb][brow][bcol + 4] = b1;
        }
        __syncthreads();
    }

    const int crow = m0 + tm * 8;
    const int ccol = n0 + tn * 8;
    float bv[8];
    if (ep) {
        float4 q0 = *(const float4*)(bias + ccol);
        float4 q1 = *(const float4*)(bias + ccol + 4);
        bv[0] = q0.x; bv[1] = q0.y; bv[2] = q0.z; bv[3] = q0.w;
        bv[4] = q1.x; bv[5] = q1.y; bv[6] = q1.z; bv[7] = q1.w;
    } else {
#pragma unroll
        for (int j = 0; j < 8; ++j) bv[j] = 0.f;
    }

#pragma unroll
    for (int i = 0; i < 4; ++i) {
        float r0[8], r1[8];
#pragma unroll
        for (int j = 0; j < 8; ++j) {
            float2 v = unpackf2(acc[i][j]);
            r0[j] = v.x + bv[j];
            r1[j] = v.y + bv[j];
        }
        if (ep == 1) {
#pragma unroll
            for (int j = 0; j < 8; ++j) {
                r0[j] = fmaxf(r0[j], 0.f);
                r1[j] = fmaxf(r1[j], 0.f);
            }
        } else if (ep == 3) {
#pragma unroll
            for (int j = 0; j < 8; ++j) {
                r0[j] = softplusf(r0[j]);
                r1[j] = softplusf(r1[j]);
            }
        }
        float* p0 = C + (size_t)(crow + 2 * i)     * N + ccol;
        float* p1 = C + (size_t)(crow + 2 * i + 1) * N + ccol;
        *(float4*)p0       = make_float4(r0[0], r0[1], r0[2], r0[3]);
        *(float4*)(p0 + 4) = make_float4(r0[4], r0[5], r0[6], r0[7]);
        *(float4*)p1       = make_float4(r1[0], r1[1], r1[2], r1[3]);
        *(float4*)(p1 + 4) = make_float4(r1[4], r1[5], r1[6], r1[7]);
    }
}

/* ================= SIMT GEMM (xproj: N=64), z-batched ============== */
__global__ __launch_bounds__(256)
void gemm_kernel(const float* __restrict__ A0, const float* __restrict__ A1,
                 int lda,
                 const float* __restrict__ B0, const float* __restrict__ B1,
                 int N, int K, float* __restrict__ C, size_t strideC)
{
    __shared__ float As[16][68];
    __shared__ float Bs[16][68];

    const int z = blockIdx.z;
    const float* A = z ? A1 : A0;
    const float* B = z ? B1 : B0;
    C += (size_t)z * strideC;

    const int tid  = threadIdx.x;
    const int tx   = tid & 15;
    const int ty   = tid >> 4;
    const int row0 = blockIdx.y * 64;
    const int col0 = blockIdx.x * 64;

    const int ar = tid >> 2;
    const int ak = (tid & 3) << 2;
    const int bk = tid >> 4;
    const int bn = (tid & 15) << 2;

    float acc[4][4];
#pragma unroll
    for (int i = 0; i < 4; ++i)
#pragma unroll
        for (int j = 0; j < 4; ++j) acc[i][j] = 0.f;

    for (int k0 = 0; k0 < K; k0 += 16) {
        float4 av = *(const float4*)(A + (size_t)(row0 + ar) * lda + k0 + ak);
        As[ak + 0][ar] = av.x;
        As[ak + 1][ar] = av.y;
        As[ak + 2][ar] = av.z;
        As[ak + 3][ar] = av.w;
        *(float4*)&Bs[bk][bn] =
            *(const float4*)(B + (size_t)(k0 + bk) * N + col0 + bn);
        __syncthreads();

#pragma unroll
        for (int kk = 0; kk < 16; ++kk) {
            float4 a = *(const float4*)&As[kk][ty << 2];
            float4 b = *(const float4*)&Bs[kk][tx << 2];
            float ai[4] = {a.x, a.y, a.z, a.w};
            float bj[4] = {b.x, b.y, b.z, b.w};
#pragma unroll
            for (int i = 0; i < 4; ++i)
#pragma unroll
                for (int j = 0; j < 4; ++j)
                    acc[i][j] = fmaf(ai[i], bj[j], acc[i][j]);
        }
        __syncthreads();
    }

    const int m0 = row0 + (ty << 2);
    const int n0 = col0 + (tx << 2);
#pragma unroll
    for (int i = 0; i < 4; ++i)
        *(float4*)(C + (size_t)(m0 + i) * N + n0) =
            make_float4(acc[i][0], acc[i][1], acc[i][2], acc[i][3]);
}

/* ------------------------------------------------------------------ */
__global__ void flip_kernel(const float* __restrict__ x, float* __restrict__ xb)
{
    int idx = blockIdx.x * 256 + threadIdx.x;
    int c = idx & 127;
    int r = idx >> 7;
    int b = r >> 11;
    int l = r & 2047;
    ((float4*)xb)[idx] =
        ((const float4*)x)[(size_t)(((b << 11) + (2047 - l)) << 7) + c];
}

/* ------------------------------------------------------------------ */
/* depthwise causal conv (K=4) + bias + silu, z-batched                */
__global__ void conv_silu_kernel(const float* __restrict__ xz,
                                 const float* __restrict__ cw0,
                                 const float* __restrict__ cb0,
                                 const float* __restrict__ cw1,
                                 const float* __restrict__ cb1,
                                 float* __restrict__ xc)
{
    const int dir = blockIdx.z;
    const float* cw = dir ? cw1 : cw0;
    const float* cb = dir ? cb1 : cb0;
    xz += (size_t)dir * BLr * 2 * ED_;
    xc += (size_t)dir * BLr * ED_;

    int idx = blockIdx.x * 256 + threadIdx.x;
    int e = idx & 1023;
    int r = idx >> 10;
    int l = r & 2047;
    int b = r >> 11;
    float s = cb[e];
#pragma unroll
    for (int k = 0; k < 4; ++k) {
        int ll = l + k - 3;
        if (ll >= 0)
            s = fmaf(xz[((size_t)((b << 11) + ll) << 11) + e], cw[(e << 2) + k], s);
    }
    xc[idx] = siluf(s);
}

/* ================= chunked selective scan ========================== */
/* Pass A: local scans per (chain, chunk), h_in = 0; emit h_out, PIdA  */
__global__ __launch_bounds__(256)
void scanA_kernel(const float* __restrict__ delta,
                  const float* __restrict__ xc,
                  const float* __restrict__ dbl,
                  const float* __restrict__ Alog0,
                  const float* __restrict__ Alog1,
                  float* __restrict__ hloc, float* __restrict__ aprod)
{
    const int dir  = blockIdx.y;
    const int warp = blockIdx.x * 8 + (threadIdx.x >> 5);   /* 0..16383 */
    const int lane = threadIdx.x & 31;
    const int half = lane >> 4;
    const int n    = lane & 15;
    const int chunk = warp >> 10;
    const int chain = ((warp & 1023) << 1) + half;
    const int b = chain >> 10;
    const int e = chain & 1023;

    const float* Alog = dir ? Alog1 : Alog0;
    delta += (size_t)dir * BLr * ED_;
    xc    += (size_t)dir * BLr * ED_;
    dbl   += (size_t)dir * BLr * 64;

    const float a = -expf(Alog[(e << 4) + n]);
    float h = 0.f, ap = 1.f;
    const int r0 = (b << 11) + chunk * CLEN;

    for (int l = 0; l < CLEN; l += 4) {
        float d[4], xv[4], bv[4];
#pragma unroll
        for (int s = 0; s < 4; ++s) {
            int row = r0 + l + s;
            d[s]  = __ldg(&delta[((size_t)row << 10) + e]);
            xv[s] = __ldg(&xc   [((size_t)row << 10) + e]);
            bv[s] = __ldg(&dbl  [(row << 6) + 32 + n]);
        }
#pragma unroll
        for (int s = 0; s < 4; ++s) {
            float dA = __expf(d[s] * a);
            h = fmaf(dA, h, d[s] * xv[s] * bv[s]);
            ap *= dA;
        }
    }
    size_t idx = ((size_t)dir * NCHUNK + chunk) * (NCHAIN * NS)
               + chain * NS + n;
    hloc[idx]  = h;
    aprod[idx] = ap;
}

/* Pass B: sequential carry combine across chunks (per chain,n)        */
__global__ void scanB_kernel(const float* __restrict__ hloc,
                             const float* __restrict__ aprod,
                             float* __restrict__ hin)
{
    const int dir = blockIdx.y;
    const int t = blockIdx.x * 256 + threadIdx.x;   /* 0..32767 */
    const size_t base = (size_t)dir * NCHUNK * NCHAIN * NS;
    float h = 0.f;
#pragma unroll
    for (int c = 0; c < NCHUNK; ++c) {
        size_t idx = base + (size_t)c * NCHAIN * NS + t;
        hin[idx] = h;
        h = fmaf(aprod[idx], h, hloc[idx]);
    }
}

/* Pass C: local scans with correct carry; emit gated y                */
__global__ __launch_bounds__(256)
void scanC_kernel(const float* __restrict__ delta,
                  const float* __restrict__ xc,
                  const float* __restrict__ dbl,
                  const float* __restrict__ xz,
                  const float* __restrict__ Alog0,
                  const float* __restrict__ Alog1,
                  const float* __restrict__ Dp0,
                  const float* __restrict__ Dp1,
                  const float* __restrict__ hin,
                  float* __restrict__ y)
{
    const int dir  = blockIdx.y;
    const int warp = blockIdx.x * 8 + (threadIdx.x >> 5);
    const int lane = threadIdx.x & 31;
    const int half = lane >> 4;
    const int n    = lane & 15;
    const int chunk = warp >> 10;
    const int chain = ((warp & 1023) << 1) + half;
    const int b = chain >> 10;
    const int e = chain & 1023;

    const float* Alog = dir ? Alog1 : Alog0;
    const float* Dp   = dir ? Dp1   : Dp0;
    delta += (size_t)dir * BLr * ED_;
    xc    += (size_t)dir * BLr * ED_;
    y     += (size_t)dir * BLr * ED_;
    dbl   += (size_t)dir * BLr * 64;
    xz    += (size_t)dir * BLr * 2 * ED_;

    const float a  = -expf(Alog[(e << 4) + n]);
    const float dc = Dp[e];
    float h = hin[((size_t)dir * NCHUNK + chunk) * (NCHAIN * NS)
                  + chain * NS + n];
    const int r0 = (b << 11) + chunk * CLEN;

    for (int l = 0; l < CLEN; l += 4) {
        float d[4], xv[4], bv[4], cv[4];
#pragma unroll
        for (int s = 0; s < 4; ++s) {
            int row = r0 + l + s;
            d[s]  = __ldg(&delta[((size_t)row << 10) + e]);
            xv[s] = __ldg(&xc   [((size_t)row << 10) + e]);
            bv[s] = __ldg(&dbl  [(row << 6) + 32 + n]);
            cv[s] = __ldg(&dbl  [(row << 6) + 48 + n]);
        }
        float p[4];
#pragma unroll
        for (int s = 0; s < 4; ++s) {
            float dA = __expf(d[s] * a);
            h = fmaf(dA, h, d[s] * xv[s] * bv[s]);
            p[s] = h * cv[s];
        }
#pragma unroll
        for (int o = 1; o < 16; o <<= 1) {
#pragma unroll
            for (int s = 0; s < 4; ++s)
                p[s] += __shfl_xor_sync(0xffffffffu, p[s], o);
        }
        if (n == 0) {
#pragma unroll
            for (int s = 0; s < 4; ++s) {
                int row = r0 + l + s;
                float zv = xz[((size_t)row << 11) + 1024 + e];
                y[((size_t)row << 10) + e] = (p[s] + xv[s] * dc) * siluf(zv);
            }
        }
    }
}

/* ------------------------------------------------------------------ */
__global__ __launch_bounds__(128)
void ln_kernel(float* __restrict__ U, const float* __restrict__ g,
               const float* __restrict__ bb)
{
    int row = blockIdx.x;
    float4* p = (float4*)(U + (size_t)row * DM);
    int tid = threadIdx.x;
    int lane = tid & 31, w = tid >> 5;
    __shared__ float red[4];

    float4 v = p[tid];
    float s = v.x + v.y + v.z + v.w;
#pragma unroll
    for (int o = 16; o; o >>= 1) s += __shfl_xor_sync(0xffffffffu, s, o);
    if (!lane) red[w] = s;
    __syncthreads();
    float mu = (red[0] + red[1] + red[2] + red[3]) * (1.f / 512.f);

    float dx = v.x - mu, dy = v.y - mu, dz = v.z - mu, dw = v.w - mu;
    float s2 = dx*dx + dy*dy + dz*dz + dw*dw;
#pragma unroll
    for (int o = 16; o; o >>= 1) s2 += __shfl_xor_sync(0xffffffffu, s2, o);
    __syncthreads();
    if (!lane) red[w] = s2;
    __syncthreads();
    float var  = (red[0] + red[1] + red[2] + red[3]) * (1.f / 512.f);
    float rstd = rsqrtf(var + 1e-5f);

    int c = tid << 2;
    float4 go = *(const float4*)(g + c);
    float4 bo = *(const float4*)(bb + c);
    float4 o;
    o.x = dx * rstd * go.x + bo.x;
    o.y = dy * rstd * go.y + bo.y;
    o.z = dz * rstd * go.z + bo.z;
    o.w = dw * rstd * go.w + bo.w;
    p[tid] = o;
}

/* ------------------------------------------------------------------ */
__global__ void final_kernel(const float* __restrict__ V2,
                             const float* __restrict__ U,
                             float* __restrict__ out)
{
    int idx = blockIdx.x * 256 + threadIdx.x;
    const int off = (BLr * DM) >> 2;
    float4 a = ((const float4*)V2)[idx];
    float4 b = ((const float4*)V2)[idx + off];
    float4 c = ((const float4*)U)[idx];
    float4 d = ((const float4*)U)[idx + off];
    float4 o;
    o.x = a.x + b.x + c.x + d.x;
    o.y = a.y + b.y + c.y + d.y;
    o.z = a.z + b.z + c.z + d.z;
    o.w = a.w + b.w + c.w + d.w;
    ((float4*)out)[idx] = o;
}

/* ------------------------------------------------------------------ */
extern "C" void kernel_launch(void* const* d_in, const int* in_sizes, int n_in,
                              void* d_out, int out_size)
{
    (void)in_sizes; (void)n_in; (void)out_size;

    float *xb, *xz, *xc, *dbl, *delta, *y, *U, *Vh, *V2;
    float *hloc, *aprod, *hin;
    cudaGetSymbolAddress((void**)&xb,    g_xb);
    cudaGetSymbolAddress((void**)&xz,    g_xz);
    cudaGetSymbolAddress((void**)&xc,    g_xc);
    cudaGetSymbolAddress((void**)&dbl,   g_dbl);
    cudaGetSymbolAddress((void**)&delta, g_delta);
    cudaGetSymbolAddress((void**)&y,     g_y);
    cudaGetSymbolAddress((void**)&U,     g_U);
    cudaGetSymbolAddress((void**)&Vh,    g_Vh);
    cudaGetSymbolAddress((void**)&V2,    g_V2);
    cudaGetSymbolAddress((void**)&hloc,  g_hloc);
    cudaGetSymbolAddress((void**)&aprod, g_aprod);
    cudaGetSymbolAddress((void**)&hin,   g_hin);

    const float* x = (const float*)d_in[0];
    const float* norm1_g = (const float*)d_in[19];
    const float* norm1_b = (const float*)d_in[20];
    const float* ffn_w1  = (const float*)d_in[23];
    const float* ffn_b1  = (const float*)d_in[24];
    const float* ffn_w2  = (const float*)d_in[25];
    const float* ffn_b2  = (const float*)d_in[26];

    const float* W[2][9];
    for (int dir = 0; dir < 2; ++dir)
        for (int k = 0; k < 9; ++k)
            W[dir][k] = (const float*)d_in[1 + dir * 9 + k];

    /* #1: flip x along L for backward direction */
    flip_kernel<<<(BLr * DM / 4) / 256, 256>>>(x, xb);

    /* #2: xz_z = A_z @ in_w_z : 4096 x 2048 x 512, z-batched */
    f2_gemm<<<dim3(2 * ED_ / 128, BLr / 128, 2), 256>>>(
        x, xb, DM, W[0][0], W[1][0], 2 * ED_, DM,
        xz, (size_t)BLr * 2 * ED_, nullptr, nullptr, 0);

    /* #3: depthwise conv + silu, z-batched */
    conv_silu_kernel<<<dim3((BLr * ED_) / 256, 1, 2), 256>>>(
        xz, W[0][1], W[0][2], W[1][1], W[1][2], xc);

    /* #4: dbl = xc @ xproj_w : 4096 x 64 x 1024, z-batched (SIMT) */
    gemm_kernel<<<dim3(1, BLr / 64, 2), 256>>>(
        xc, xc + (size_t)BLr * ED_, ED_, W[0][3], W[1][3], 64, ED_,
        dbl, (size_t)BLr * 64);

    /* #5: delta = softplus(dt @ dt_w + dt_b) : 4096 x 1024 x 32 */
    f2_gemm<<<dim3(ED_ / 128, BLr / 128, 2), 256>>>(
        dbl, dbl + (size_t)BLr * 64, 64, W[0][4], W[1][4], ED_, DTR,
        delta, (size_t)BLr * ED_, W[0][5], W[1][5], 3);

    /* #6-8: chunked selective scan (both dirs) */
    scanA_kernel<<<dim3(2048, 2), 256>>>(
        delta, xc, dbl, W[0][6], W[1][6], hloc, aprod);
    scanB_kernel<<<dim3(128, 2), 256>>>(hloc, aprod, hin);
    scanC_kernel<<<dim3(2048, 2), 256>>>(
        delta, xc, dbl, xz, W[0][6], W[1][6], W[0][7], W[1][7], hin, y);

    /* #9: U_z = y_z @ out_w_z : 4096 x 512 x 1024, z-batched */
    f2_gemm<<<dim3(DM / 128, BLr / 128, 2), 256>>>(
        y, y + (size_t)BLr * ED_, ED_, W[0][8], W[1][8], DM, ED_,
        U, (size_t)BLr * DM, nullptr, nullptr, 0);

    /* #10: layernorm on forward branch only */
    ln_kernel<<<BLr, 128>>>(U, norm1_g, norm1_b);

    /* #11-12: FFN batched over both directions: 8192 rows */
    f2_gemm<<<dim3(DFF / 128, 2 * BLr / 128, 1), 256>>>(
        U, U, DM, ffn_w1, ffn_w1, DFF, DM,
        Vh, 0, ffn_b1, ffn_b1, 1);
    f2_gemm<<<dim3(DM / 128, 2 * BLr / 128, 1), 256>>>(
        Vh, Vh, DFF, ffn_w2, ffn_w2, DM, DFF,
        V2, 0, ffn_b2, ffn_b2, 2);

    /* #13: out = V2_f + V2_b + U_f + U_b */
    final_kernel<<<(BLr * DM / 4) / 256, 256>>>(V2, U, (float*)d_out);
}

// round 6
// speedup vs baseline: 2.3512x; 1.0837x over previous
#include <cuda_runtime.h>
#include <cstdint>

#define Bb     2
#define LL     2048
#define DM     512
#define ED_    1024
#define NS     16
#define DTR    32
#define DFF    1024
#define BLr    (Bb*LL)            /* 4096 rows */
#define NCHUNK 16
#define CLEN   (LL/NCHUNK)        /* 128 */
#define NCHAIN 2048
#define KSPL   8                  /* xproj split-K factor */

typedef unsigned long long ull;

/* ------------------------------------------------------------------ */
__device__ float g_xb   [BLr*DM];
__device__ float g_xz   [2*BLr*2*ED_];
__device__ float g_xc   [2*BLr*ED_];
__device__ float g_dbl  [2*BLr*64];
__device__ float g_part [2*KSPL*BLr*64];
__device__ float g_delta[2*BLr*ED_];
__device__ float g_y    [2*BLr*ED_];
__device__ float g_U    [2*BLr*DM];
__device__ float g_Vh   [2*BLr*DFF];
__device__ float g_V2   [2*BLr*DM];
__device__ float g_hloc [2*NCHUNK*NCHAIN*NS];
__device__ float g_aprod[2*NCHUNK*NCHAIN*NS];
__device__ float g_hin  [2*NCHUNK*NCHAIN*NS];

/* ------------------------------------------------------------------ */
__device__ __forceinline__ float softplusf(float x) {
    return fmaxf(x, 0.f) + log1pf(expf(-fabsf(x)));
}
__device__ __forceinline__ float siluf(float x) {
    return x / (1.f + __expf(-x));
}
__device__ __forceinline__ uint32_t smem_u32(const void* p) {
    uint32_t a;
    asm("{ .reg .u64 t; cvta.to.shared.u64 t, %1; cvt.u32.u64 %0, t; }"
        : "=r"(a) : "l"(p));
    return a;
}
__device__ __forceinline__ ull fma2(ull a, ull b, ull c) {
    ull d;
    asm("fma.rn.f32x2 %0, %1, %2, %3;" : "=l"(d) : "l"(a), "l"(b), "l"(c));
    return d;
}
__device__ __forceinline__ ull packf2(float lo, float hi) {
    ull r;
    asm("mov.b64 %0, {%1, %2};" : "=l"(r) : "f"(lo), "f"(hi));
    return r;
}
__device__ __forceinline__ float2 unpackf2(ull v) {
    float lo, hi;
    asm("mov.b64 {%0, %1}, %2;" : "=f"(lo), "=f"(hi) : "l"(v));
    return make_float2(lo, hi);
}
__device__ __forceinline__ void cp16(uint32_t dst, const void* src) {
    asm volatile("cp.async.ca.shared.global [%0], [%1], 16;"
                 :: "r"(dst), "l"(src));
}
__device__ __forceinline__ void cp_commit() {
    asm volatile("cp.async.commit_group;");
}
__device__ __forceinline__ void cp_wait0() {
    asm volatile("cp.async.wait_group 0;" ::: "memory");
}

/* ================= f32x2 GEMM (z-batched over 2 dirs) ============== */
/* C[z][M,N] = A_z[M,K](lda) @ B_z[K,N] fp32.                          */
/* 128x128x16 tiles, 256 threads, 8m x 4 n-pairs per thread (FFMA2).   */
/* B smem filled by cp.async; n-pair LDS.64 reads are conflict-free.   */
/* ep: 0 none, 1 bias+relu, 2 bias, 3 softplus(bias+x)                 */

__global__ void __launch_bounds__(256, 2)
f2_gemm(const float* __restrict__ A0, const float* __restrict__ A1, int lda,
        const float* __restrict__ B0, const float* __restrict__ B1,
        int N, int K,
        float* __restrict__ C, size_t strideC,
        const float* __restrict__ bias0, const float* __restrict__ bias1,
        int ep)
{
    __shared__ float As[2][16][132];
    __shared__ float Bs[2][16][132];

    const int z = blockIdx.z;
    const float* A = z ? A1 : A0;
    const float* B = z ? B1 : B0;
    const float* bias = z ? bias1 : bias0;
    C += (size_t)z * strideC;

    const int tid = threadIdx.x;
    const int m0 = blockIdx.y * 128;
    const int n0 = blockIdx.x * 128;
    const int tm = tid >> 4;          /* 0..15: m-rows tm*8..+7 */
    const int tn = tid & 15;          /* 0..15: n-pairs tn*2+32jj */

    const int arow = tid >> 1;
    const int acol = (tid & 1) * 8;
    const int brow = tid >> 4;            /* 0..15 */
    const int bcol = (tid & 15) * 8;      /* 0..120 */

    const float* gA = A + (size_t)(m0 + arow) * lda + acol;
    const float* gB = B + (size_t)brow * N + n0 + bcol;
    const uint32_t bs0 = smem_u32(&Bs[0][0][0]) + (uint32_t)((brow * 132 + bcol) * 4);
    const uint32_t bsStride = 16u * 132u * 4u;

    float4 a0, a1;

    /* prolog: tile 0 */
    a0 = *(const float4*)gA;  a1 = *(const float4*)(gA + 4);
    As[0][acol + 0][arow] = a0.x;  As[0][acol + 1][arow] = a0.y;
    As[0][acol + 2][arow] = a0.z;  As[0][acol + 3][arow] = a0.w;
    As[0][acol + 4][arow] = a1.x;  As[0][acol + 5][arow] = a1.y;
    As[0][acol + 6][arow] = a1.z;  As[0][acol + 7][arow] = a1.w;
    cp16(bs0,      gB);
    cp16(bs0 + 16, gB + 4);
    cp_commit();
    cp_wait0();
    __syncthreads();

    ull acc[8][4];
#pragma unroll
    for (int i = 0; i < 8; ++i)
#pragma unroll
        for (int j = 0; j < 4; ++j) acc[i][j] = 0ull;

    const int NIT = K >> 4;
    for (int it = 0; it < NIT; ++it) {
        const int buf = it & 1;
        if (it + 1 < NIT) {
            const float* pA = gA + (it + 1) * 16;
            a0 = *(const float4*)pA;  a1 = *(const float4*)(pA + 4);
            const float* pB = gB + (size_t)(it + 1) * 16 * N;
            const uint32_t d = bs0 + (buf ^ 1) * bsStride;
            cp16(d,      pB);
            cp16(d + 16, pB + 4);
            cp_commit();
        }
#pragma unroll
        for (int k = 0; k < 16; ++k) {
            float4 f0 = *(const float4*)&As[buf][k][tm * 8];
            float4 f1 = *(const float4*)&As[buf][k][tm * 8 + 4];
            ull a2[8];
            a2[0] = packf2(f0.x, f0.x);  a2[1] = packf2(f0.y, f0.y);
            a2[2] = packf2(f0.z, f0.z);  a2[3] = packf2(f0.w, f0.w);
            a2[4] = packf2(f1.x, f1.x);  a2[5] = packf2(f1.y, f1.y);
            a2[6] = packf2(f1.z, f1.z);  a2[7] = packf2(f1.w, f1.w);
            ull b2[4];
#pragma unroll
            for (int jj = 0; jj < 4; ++jj)
                b2[jj] = *(const ull*)&Bs[buf][k][tn * 2 + 32 * jj];
#pragma unroll
            for (int i = 0; i < 8; ++i)
#pragma unroll
                for (int jj = 0; jj < 4; ++jj)
                    acc[i][jj] = fma2(a2[i], b2[jj], acc[i][jj]);
        }
        if (it + 1 < NIT) {
            const int nb = buf ^ 1;
            As[nb][acol + 0][arow] = a0.x;  As[nb][acol + 1][arow] = a0.y;
            As[nb][acol + 2][arow] = a0.z;  As[nb][acol + 3][arow] = a0.w;
            As[nb][acol + 4][arow] = a1.x;  As[nb][acol + 5][arow] = a1.y;
            As[nb][acol + 6][arow] = a1.z;  As[nb][acol + 7][arow] = a1.w;
            cp_wait0();
        }
        __syncthreads();
    }

    /* ---- epilogue: rows m0+tm*8..+7, n-pairs n0+tn*2+32jj ---- */
    const int crow = m0 + tm * 8;
    float2 bv[4];
#pragma unroll
    for (int jj = 0; jj < 4; ++jj) {
        if (ep) bv[jj] = *(const float2*)(bias + n0 + tn * 2 + 32 * jj);
        else    bv[jj] = make_float2(0.f, 0.f);
    }
#pragma unroll
    for (int i = 0; i < 8; ++i) {
        float* Crow = C + (size_t)(crow + i) * N + n0 + tn * 2;
#pragma unroll
        for (int jj = 0; jj < 4; ++jj) {
            float2 v = unpackf2(acc[i][jj]);
            v.x += bv[jj].x;  v.y += bv[jj].y;
            if (ep == 1) {
                v.x = fmaxf(v.x, 0.f);  v.y = fmaxf(v.y, 0.f);
            } else if (ep == 3) {
                v.x = softplusf(v.x);   v.y = softplusf(v.y);
            }
            *(float2*)(Crow + 32 * jj) = v;
        }
    }
}

/* ================= xproj split-K (N=64, K=1024, 8 slices) ========== */
__global__ __launch_bounds__(256)
void xproj_kernel(const float* __restrict__ xc,
                  const float* __restrict__ B0, const float* __restrict__ B1,
                  float* __restrict__ part)
{
    __shared__ float As[16][68];
    __shared__ float Bs[16][68];

    const int ks  = blockIdx.x;       /* 0..7  */
    const int dir = blockIdx.z;
    const float* A = xc + (size_t)dir * BLr * ED_;
    const float* B = dir ? B1 : B0;
    float* P = part + ((size_t)dir * KSPL + ks) * BLr * 64;

    const int tid  = threadIdx.x;
    const int tx   = tid & 15;
    const int ty   = tid >> 4;
    const int row0 = blockIdx.y * 64;
    const int kbase = ks * (ED_ / KSPL);   /* 128 per slice */

    const int ar = tid >> 2;
    const int ak = (tid & 3) << 2;
    const int bk = tid >> 4;
    const int bn = (tid & 15) << 2;

    float acc[4][4];
#pragma unroll
    for (int i = 0; i < 4; ++i)
#pragma unroll
        for (int j = 0; j < 4; ++j) acc[i][j] = 0.f;

    for (int k0 = kbase; k0 < kbase + ED_ / KSPL; k0 += 16) {
        float4 av = *(const float4*)(A + (size_t)(row0 + ar) * ED_ + k0 + ak);
        As[ak + 0][ar] = av.x;
        As[ak + 1][ar] = av.y;
        As[ak + 2][ar] = av.z;
        As[ak + 3][ar] = av.w;
        *(float4*)&Bs[bk][bn] =
            *(const float4*)(B + (size_t)(k0 + bk) * 64 + bn);
        __syncthreads();

#pragma unroll
        for (int kk = 0; kk < 16; ++kk) {
            float4 a = *(const float4*)&As[kk][ty << 2];
            float4 b = *(const float4*)&Bs[kk][tx << 2];
            float ai[4] = {a.x, a.y, a.z, a.w};
            float bj[4] = {b.x, b.y, b.z, b.w};
#pragma unroll
            for (int i = 0; i < 4; ++i)
#pragma unroll
                for (int j = 0; j < 4; ++j)
                    acc[i][j] = fmaf(ai[i], bj[j], acc[i][j]);
        }
        __syncthreads();
    }

    const int m0 = row0 + (ty << 2);
    const int n0 = tx << 2;
#pragma unroll
    for (int i = 0; i < 4; ++i)
        *(float4*)(P + (size_t)(m0 + i) * 64 + n0) =
            make_float4(acc[i][0], acc[i][1], acc[i][2], acc[i][3]);
}

__global__ void xproj_reduce(const float* __restrict__ part,
                             float* __restrict__ dbl)
{
    const int idx = blockIdx.x * 256 + threadIdx.x;     /* 2*65536 float4 */
    const int dir = idx >> 16;
    const int r   = idx & 65535;
    const float4* p = (const float4*)part + (size_t)dir * KSPL * 65536 + r;
    float4 s = make_float4(0.f, 0.f, 0.f, 0.f);
#pragma unroll
    for (int ks = 0; ks < KSPL; ++ks) {
        float4 v = p[(size_t)ks * 65536];
        s.x += v.x; s.y += v.y; s.z += v.z; s.w += v.w;
    }
    ((float4*)dbl)[idx] = s;
}

/* ------------------------------------------------------------------ */
__global__ void flip_kernel(const float* __restrict__ x, float* __restrict__ xb)
{
    int idx = blockIdx.x * 256 + threadIdx.x;
    int c = idx & 127;
    int r = idx >> 7;
    int b = r >> 11;
    int l = r & 2047;
    ((float4*)xb)[idx] =
        ((const float4*)x)[(size_t)(((b << 11) + (2047 - l)) << 7) + c];
}

/* ------------------------------------------------------------------ */
__global__ void conv_silu_kernel(const float* __restrict__ xz,
                                 const float* __restrict__ cw0,
                                 const float* __restrict__ cb0,
                                 const float* __restrict__ cw1,
                                 const float* __restrict__ cb1,
                                 float* __restrict__ xc)
{
    const int dir = blockIdx.z;
    const float* cw = dir ? cw1 : cw0;
    const float* cb = dir ? cb1 : cb0;
    xz += (size_t)dir * BLr * 2 * ED_;
    xc += (size_t)dir * BLr * ED_;

    int idx = blockIdx.x * 256 + threadIdx.x;
    int e = idx & 1023;
    int r = idx >> 10;
    int l = r & 2047;
    int b = r >> 11;
    float s = cb[e];
#pragma unroll
    for (int k = 0; k < 4; ++k) {
        int ll = l + k - 3;
        if (ll >= 0)
            s = fmaf(xz[((size_t)((b << 11) + ll) << 11) + e], cw[(e << 2) + k], s);
    }
    xc[idx] = siluf(s);
}

/* ================= chunked selective scan ========================== */
__global__ __launch_bounds__(256)
void scanA_kernel(const float* __restrict__ delta,
                  const float* __restrict__ xc,
                  const float* __restrict__ dbl,
                  const float* __restrict__ Alog0,
                  const float* __restrict__ Alog1,
                  float* __restrict__ hloc, float* __restrict__ aprod)
{
    const int dir  = blockIdx.y;
    const int warp = blockIdx.x * 8 + (threadIdx.x >> 5);
    const int lane = threadIdx.x & 31;
    const int half = lane >> 4;
    const int n    = lane & 15;
    const int chunk = warp >> 10;
    const int chain = ((warp & 1023) << 1) + half;
    const int b = chain >> 10;
    const int e = chain & 1023;

    const float* Alog = dir ? Alog1 : Alog0;
    delta += (size_t)dir * BLr * ED_;
    xc    += (size_t)dir * BLr * ED_;
    dbl   += (size_t)dir * BLr * 64;

    const float a = -expf(Alog[(e << 4) + n]);
    float h = 0.f, ap = 1.f;
    const int r0 = (b << 11) + chunk * CLEN;

    for (int l = 0; l < CLEN; l += 4) {
        float d[4], xv[4], bv[4];
#pragma unroll
        for (int s = 0; s < 4; ++s) {
            int row = r0 + l + s;
            d[s]  = __ldg(&delta[((size_t)row << 10) + e]);
            xv[s] = __ldg(&xc   [((size_t)row << 10) + e]);
            bv[s] = __ldg(&dbl  [(row << 6) + 32 + n]);
        }
#pragma unroll
        for (int s = 0; s < 4; ++s) {
            float dA = __expf(d[s] * a);
            h = fmaf(dA, h, d[s] * xv[s] * bv[s]);
            ap *= dA;
        }
    }
    size_t idx = ((size_t)dir * NCHUNK + chunk) * (NCHAIN * NS)
               + chain * NS + n;
    hloc[idx]  = h;
    aprod[idx] = ap;
}

__global__ void scanB_kernel(const float* __restrict__ hloc,
                             const float* __restrict__ aprod,
                             float* __restrict__ hin)
{
    const int dir = blockIdx.y;
    const int t = blockIdx.x * 256 + threadIdx.x;
    const size_t base = (size_t)dir * NCHUNK * NCHAIN * NS;
    float h = 0.f;
#pragma unroll
    for (int c = 0; c < NCHUNK; ++c) {
        size_t idx = base + (size_t)c * NCHAIN * NS + t;
        hin[idx] = h;
        h = fmaf(aprod[idx], h, hloc[idx]);
    }
}

__global__ __launch_bounds__(256)
void scanC_kernel(const float* __restrict__ delta,
                  const float* __restrict__ xc,
                  const float* __restrict__ dbl,
                  const float* __restrict__ xz,
                  const float* __restrict__ Alog0,
                  const float* __restrict__ Alog1,
                  const float* __restrict__ Dp0,
                  const float* __restrict__ Dp1,
                  const float* __restrict__ hin,
                  float* __restrict__ y)
{
    const int dir  = blockIdx.y;
    const int warp = blockIdx.x * 8 + (threadIdx.x >> 5);
    const int lane = threadIdx.x & 31;
    const int half = lane >> 4;
    const int n    = lane & 15;
    const int chunk = warp >> 10;
    const int chain = ((warp & 1023) << 1) + half;
    const int b = chain >> 10;
    const int e = chain & 1023;

    const float* Alog = dir ? Alog1 : Alog0;
    const float* Dp   = dir ? Dp1   : Dp0;
    delta += (size_t)dir * BLr * ED_;
    xc    += (size_t)dir * BLr * ED_;
    y     += (size_t)dir * BLr * ED_;
    dbl   += (size_t)dir * BLr * 64;
    xz    += (size_t)dir * BLr * 2 * ED_;

    const float a  = -expf(Alog[(e << 4) + n]);
    const float dc = Dp[e];
    float h = hin[((size_t)dir * NCHUNK + chunk) * (NCHAIN * NS)
                  + chain * NS + n];
    const int r0 = (b << 11) + chunk * CLEN;

    for (int l = 0; l < CLEN; l += 4) {
        float d[4], xv[4], bv[4], cv[4];
#pragma unroll
        for (int s = 0; s < 4; ++s) {
            int row = r0 + l + s;
            d[s]  = __ldg(&delta[((size_t)row << 10) + e]);
            xv[s] = __ldg(&xc   [((size_t)row << 10) + e]);
            bv[s] = __ldg(&dbl  [(row << 6) + 32 + n]);
            cv[s] = __ldg(&dbl  [(row << 6) + 48 + n]);
        }
        float p[4];
#pragma unroll
        for (int s = 0; s < 4; ++s) {
            float dA = __expf(d[s] * a);
            h = fmaf(dA, h, d[s] * xv[s] * bv[s]);
            p[s] = h * cv[s];
        }
#pragma unroll
        for (int o = 1; o < 16; o <<= 1) {
#pragma unroll
            for (int s = 0; s < 4; ++s)
                p[s] += __shfl_xor_sync(0xffffffffu, p[s], o);
        }
        if (n == 0) {
#pragma unroll
            for (int s = 0; s < 4; ++s) {
                int row = r0 + l + s;
                float zv = xz[((size_t)row << 11) + 1024 + e];
                y[((size_t)row << 10) + e] = (p[s] + xv[s] * dc) * siluf(zv);
            }
        }
    }
}

/* ------------------------------------------------------------------ */
__global__ __launch_bounds__(128)
void ln_kernel(float* __restrict__ U, const float* __restrict__ g,
               const float* __restrict__ bb)
{
    int row = blockIdx.x;
    float4* p = (float4*)(U + (size_t)row * DM);
    int tid = threadIdx.x;
    int lane = tid & 31, w = tid >> 5;
    __shared__ float red[4];

    float4 v = p[tid];
    float s = v.x + v.y + v.z + v.w;
#pragma unroll
    for (int o = 16; o; o >>= 1) s += __shfl_xor_sync(0xffffffffu, s, o);
    if (!lane) red[w] = s;
    __syncthreads();
    float mu = (red[0] + red[1] + red[2] + red[3]) * (1.f / 512.f);

    float dx = v.x - mu, dy = v.y - mu, dz = v.z - mu, dw = v.w - mu;
    float s2 = dx*dx + dy*dy + dz*dz + dw*dw;
#pragma unroll
    for (int o = 16; o; o >>= 1) s2 += __shfl_xor_sync(0xffffffffu, s2, o);
    __syncthreads();
    if (!lane) red[w] = s2;
    __syncthreads();
    float var  = (red[0] + red[1] + red[2] + red[3]) * (1.f / 512.f);
    float rstd = rsqrtf(var + 1e-5f);

    int c = tid << 2;
    float4 go = *(const float4*)(g + c);
    float4 bo = *(const float4*)(bb + c);
    float4 o;
    o.x = dx * rstd * go.x + bo.x;
    o.y = dy * rstd * go.y + bo.y;
    o.z = dz * rstd * go.z + bo.z;
    o.w = dw * rstd * go.w + bo.w;
    p[tid] = o;
}

/* ------------------------------------------------------------------ */
__global__ void final_kernel(const float* __restrict__ V2,
                             const float* __restrict__ U,
                             float* __restrict__ out)
{
    int idx = blockIdx.x * 256 + threadIdx.x;
    const int off = (BLr * DM) >> 2;
    float4 a = ((const float4*)V2)[idx];
    float4 b = ((const float4*)V2)[idx + off];
    float4 c = ((const float4*)U)[idx];
    float4 d = ((const float4*)U)[idx + off];
    float4 o;
    o.x = a.x + b.x + c.x + d.x;
    o.y = a.y + b.y + c.y + d.y;
    o.z = a.z + b.z + c.z + d.z;
    o.w = a.w + b.w + c.w + d.w;
    ((float4*)out)[idx] = o;
}

/* ------------------------------------------------------------------ */
extern "C" void kernel_launch(void* const* d_in, const int* in_sizes, int n_in,
                              void* d_out, int out_size)
{
    (void)in_sizes; (void)n_in; (void)out_size;

    float *xb, *xz, *xc, *dbl, *part, *delta, *y, *U, *Vh, *V2;
    float *hloc, *aprod, *hin;
    cudaGetSymbolAddress((void**)&xb,    g_xb);
    cudaGetSymbolAddress((void**)&xz,    g_xz);
    cudaGetSymbolAddress((void**)&xc,    g_xc);
    cudaGetSymbolAddress((void**)&dbl,   g_dbl);
    cudaGetSymbolAddress((void**)&part,  g_part);
    cudaGetSymbolAddress((void**)&delta, g_delta);
    cudaGetSymbolAddress((void**)&y,     g_y);
    cudaGetSymbolAddress((void**)&U,     g_U);
    cudaGetSymbolAddress((void**)&Vh,    g_Vh);
    cudaGetSymbolAddress((void**)&V2,    g_V2);
    cudaGetSymbolAddress((void**)&hloc,  g_hloc);
    cudaGetSymbolAddress((void**)&aprod, g_aprod);
    cudaGetSymbolAddress((void**)&hin,   g_hin);

    const float* x = (const float*)d_in[0];
    const float* norm1_g = (const float*)d_in[19];
    const float* norm1_b = (const float*)d_in[20];
    const float* ffn_w1  = (const float*)d_in[23];
    const float* ffn_b1  = (const float*)d_in[24];
    const float* ffn_w2  = (const float*)d_in[25];
    const float* ffn_b2  = (const float*)d_in[26];

    const float* W[2][9];
    for (int dir = 0; dir < 2; ++dir)
        for (int k = 0; k < 9; ++k)
            W[dir][k] = (const float*)d_in[1 + dir * 9 + k];

    /* #1: flip x along L for backward direction */
    flip_kernel<<<(BLr * DM / 4) / 256, 256>>>(x, xb);

    /* #2: xz_z = A_z @ in_w_z : 4096 x 2048 x 512, z-batched */
    f2_gemm<<<dim3(2 * ED_ / 128, BLr / 128, 2), 256>>>(
        x, xb, DM, W[0][0], W[1][0], 2 * ED_, DM,
        xz, (size_t)BLr * 2 * ED_, nullptr, nullptr, 0);

    /* #3: depthwise conv + silu */
    conv_silu_kernel<<<dim3((BLr * ED_) / 256, 1, 2), 256>>>(
        xz, W[0][1], W[0][2], W[1][1], W[1][2], xc);

    /* #4-5: dbl = xc @ xproj_w, split-K 8 + reduce */
    xproj_kernel<<<dim3(KSPL, BLr / 64, 2), 256>>>(
        xc, W[0][3], W[1][3], part);
    xproj_reduce<<<(2 * BLr * 64 / 4) / 256, 256>>>(part, dbl);

    /* #6: delta = softplus(dt @ dt_w + dt_b) : 4096 x 1024 x 32 */
    f2_gemm<<<dim3(ED_ / 128, BLr / 128, 2), 256>>>(
        dbl, dbl + (size_t)BLr * 64, 64, W[0][4], W[1][4], ED_, DTR,
        delta, (size_t)BLr * ED_, W[0][5], W[1][5], 3);

    /* #7-9: chunked selective scan */
    scanA_kernel<<<dim3(2048, 2), 256>>>(
        delta, xc, dbl, W[0][6], W[1][6], hloc, aprod);
    scanB_kernel<<<dim3(128, 2), 256>>>(hloc, aprod, hin);
    scanC_kernel<<<dim3(2048, 2), 256>>>(
        delta, xc, dbl, xz, W[0][6], W[1][6], W[0][7], W[1][7], hin, y);

    /* #10: U_z = y_z @ out_w_z : 4096 x 512 x 1024 */
    f2_gemm<<<dim3(DM / 128, BLr / 128, 2), 256>>>(
        y, y + (size_t)BLr * ED_, ED_, W[0][8], W[1][8], DM, ED_,
        U, (size_t)BLr * DM, nullptr, nullptr, 0);

    /* #11: layernorm on forward branch only */
    ln_kernel<<<BLr, 128>>>(U, norm1_g, norm1_b);

    /* #12-13: FFN batched over both directions: 8192 rows */
    f2_gemm<<<dim3(DFF / 128, 2 * BLr / 128, 1), 256>>>(
        U, U, DM, ffn_w1, ffn_w1, DFF, DM,
        Vh, 0, ffn_b1, ffn_b1, 1);
    f2_gemm<<<dim3(DM / 128, 2 * BLr / 128, 1), 256>>>(
        Vh, Vh, DFF, ffn_w2, ffn_w2, DM, DFF,
        V2, 0, ffn_b2, ffn_b2, 2);

    /* #14: out = V2_f + V2_b + U_f + U_b */
    final_kernel<<<(BLr * DM / 4) / 256, 256>>>(V2, U, (float*)d_out);
}